// round 16
// baseline (speedup 1.0000x reference)
#include <cuda_runtime.h>
#include <cuda_fp16.h>
#include <cstdint>

#define NN  50000
#define NE  800000
#define NET 850000   // NE + NN self loops

typedef __half fp16;

// ---------------- scratch (static device globals; no allocs allowed) ----------
__device__ float g_f1[(size_t)NN * 256];     // layer-1 output (f32, gather source)
__device__ fp16  g_a1hi[(size_t)NN * 256], g_a1lo[(size_t)NN * 256];  // agg1 split
__device__ fp16  g_a2hi[(size_t)NN * 512], g_a2lo[(size_t)NN * 512];  // agg2 split
__device__ fp16  g_w1[256 * 128];            // W1^T [N=256,K=128] fp16
__device__ fp16  g_w2[512 * 256];            // W2^T [N=512,K=256] fp16
__device__ float g_vas1[2 * 128], g_vad1[2 * 128];   // W1_h @ a vectors
__device__ float g_vas2[2 * 256], g_vad2[2 * 256];
__device__ float g_sc1[256], g_sh1[256];     // fused bias+BN scale/shift
__device__ float g_sc2[512], g_sh2[512];
__device__ float g_es1[NN * 2], g_ed1[NN * 2];
__device__ float g_es2[NN * 2], g_ed2[NN * 2];
__device__ float g_ew[(size_t)2 * NET];      // per-edge (head0,head1) leaky logits
__device__ int   g_deg[NN];
__device__ int   g_off[NN + 1];
__device__ int   g_cur[NN];
__device__ int   g_csr[NET];                 // src per CSR slot (grouped by dst)

// ---------------- PTX helpers (arch-generic: ldmatrix + mma.sync) -------------
__device__ __forceinline__ uint32_t s2u(const void* p) {
    uint32_t a;
    asm("{ .reg .u64 t; cvta.to.shared.u64 t, %1; cvt.u32.u64 %0, t; }"
        : "=r"(a) : "l"(p));
    return a;
}

__device__ __forceinline__ void ldsm4(uint32_t* r, uint32_t addr) {
    asm volatile("ldmatrix.sync.aligned.m8n8.x4.shared.b16 {%0,%1,%2,%3}, [%4];"
                 : "=r"(r[0]), "=r"(r[1]), "=r"(r[2]), "=r"(r[3]) : "r"(addr));
}

__device__ __forceinline__ void mma16816h(float* d, const uint32_t* a,
                                          uint32_t b0, uint32_t b1) {
    asm volatile(
        "mma.sync.aligned.m16n8k16.row.col.f32.f16.f16.f32 "
        "{%0,%1,%2,%3}, {%4,%5,%6,%7}, {%8,%9}, {%0,%1,%2,%3};"
        : "+f"(d[0]), "+f"(d[1]), "+f"(d[2]), "+f"(d[3])
        : "r"(a[0]), "r"(a[1]), "r"(a[2]), "r"(a[3]), "r"(b0), "r"(b1));
}

// ---------------- W^T fp16 conversion -----------------------------------------
__global__ void k_cvtT(const float* __restrict__ W, fp16* __restrict__ T,
                       int K, int N) {
    int i = blockIdx.x * blockDim.x + threadIdx.x;
    if (i >= K * N) return;
    int k = i / N, n = i % N;
    T[(size_t)n * K + k] = __float2half_rn(W[i]);
}

// ---------------- prep 0: deg zero + BN coefs (elementwise) -------------------
__global__ void k_pre0(const float* __restrict__ b1, const float* __restrict__ g1,
                       const float* __restrict__ be1, const float* __restrict__ m1,
                       const float* __restrict__ v1,
                       const float* __restrict__ b2, const float* __restrict__ g2,
                       const float* __restrict__ be2, const float* __restrict__ m2,
                       const float* __restrict__ v2) {
    int i = blockIdx.x * blockDim.x + threadIdx.x;
    if (i < NN) g_deg[i] = 0;
    if (i < 256) {
        float sc = rsqrtf(v1[i] + 1e-5f) * g1[i];
        g_sc1[i] = sc;
        g_sh1[i] = (b1[i] - m1[i]) * sc + be1[i];
    }
    if (i >= 1024 && i < 1024 + 512) {
        int f = i - 1024;
        float sc = rsqrtf(v2[f] + 1e-5f) * g2[f];
        g_sc2[f] = sc;
        g_sh2[f] = (b2[f] - m2[f]) * sc + be2[f];
    }
}

// ---------------- va vectors: warp per output, lane-strided dot ---------------
__global__ void k_va(const float* __restrict__ W1, const float* __restrict__ as1,
                     const float* __restrict__ ad1,
                     const float* __restrict__ W2, const float* __restrict__ as2,
                     const float* __restrict__ ad2) {
    int gt = blockIdx.x * blockDim.x + threadIdx.x;
    int w = gt >> 5, lane = gt & 31;
    if (w >= 768) return;
    float s = 0.f, d = 0.f;
    if (w < 256) {
        int h = w >> 7, k = w & 127;
        const float* wr = W1 + (size_t)k * 256 + h * 128;
        const float* ar = as1 + h * 128;
        const float* dr = ad1 + h * 128;
#pragma unroll
        for (int c = lane; c < 128; c += 32) {
            float wv = wr[c];
            s += wv * ar[c];
            d += wv * dr[c];
        }
    } else {
        int j = w - 256, h = j >> 8, k = j & 255;
        const float* wr = W2 + (size_t)k * 512 + h * 256;
        const float* ar = as2 + h * 256;
        const float* dr = ad2 + h * 256;
#pragma unroll
        for (int c = lane; c < 256; c += 32) {
            float wv = wr[c];
            s += wv * ar[c];
            d += wv * dr[c];
        }
    }
#pragma unroll
    for (int o = 16; o; o >>= 1) {
        s += __shfl_xor_sync(0xffffffffu, s, o);
        d += __shfl_xor_sync(0xffffffffu, d, o);
    }
    if (lane == 0) {
        if (w < 256) { g_vas1[w] = s; g_vad1[w] = d; }
        else         { g_vas2[w - 256] = s; g_vad2[w - 256] = d; }
    }
}

// ---------------- CSR build (proven versions) ---------------------------------
__global__ void k_hist(const int* __restrict__ dst) {
    int i = blockIdx.x * blockDim.x + threadIdx.x;
    if (i >= NET) return;
    int d = (i < NE) ? dst[i] : (i - NE);
    atomicAdd(&g_deg[d], 1);
}

__global__ void k_scan() {
    __shared__ int sums[1024];
    const int t  = threadIdx.x;
    const int CH = (NN + 1023) / 1024;
    int b = t * CH, e = b + CH; if (e > NN) e = NN; if (b > NN) b = NN;
    int s = 0;
    for (int i = b; i < e; i++) s += g_deg[i];
    sums[t] = s;
    __syncthreads();
    for (int off = 1; off < 1024; off <<= 1) {
        int v = (t >= off) ? sums[t - off] : 0;
        __syncthreads();
        sums[t] += v;
        __syncthreads();
    }
    int pre = (t == 0) ? 0 : sums[t - 1];
    for (int i = b; i < e; i++) {
        g_off[i] = pre;
        g_cur[i] = pre;
        pre += g_deg[i];
    }
    if (t == 1023) g_off[NN] = NET;
}

__global__ void k_fill(const int* __restrict__ src, const int* __restrict__ dst) {
    int i = blockIdx.x * blockDim.x + threadIdx.x;
    if (i >= NET) return;
    int s, d;
    if (i < NE) { s = src[i]; d = dst[i]; }
    else        { s = d = i - NE; }
    int pos = atomicAdd(&g_cur[d], 1);
    g_csr[pos] = s;
}

// ---------------- logits: es/ed = feat . va, warp per node, 4 dots ------------
template <int K>
__global__ void k_edx(const float* __restrict__ feat, const float* __restrict__ vas,
                      const float* __restrict__ vad, float* __restrict__ es,
                      float* __restrict__ ed) {
    constexpr int NF4 = K / 128;
    int gt = blockIdx.x * blockDim.x + threadIdx.x;
    int node = gt >> 5, lane = gt & 31;
    if (node >= NN) return;
    const float4* p = (const float4*)(feat + (size_t)node * K);
    float s0 = 0.f, d0 = 0.f, s1 = 0.f, d1 = 0.f;
#pragma unroll
    for (int q = 0; q < NF4; q++) {
        int idx4 = q * 32 + lane;
        float4 xv = p[idx4];
        float4 a0 = ((const float4*)(vas))[idx4];
        float4 a1 = ((const float4*)(vas + K))[idx4];
        float4 c0 = ((const float4*)(vad))[idx4];
        float4 c1 = ((const float4*)(vad + K))[idx4];
        s0 += xv.x * a0.x + xv.y * a0.y + xv.z * a0.z + xv.w * a0.w;
        s1 += xv.x * a1.x + xv.y * a1.y + xv.z * a1.z + xv.w * a1.w;
        d0 += xv.x * c0.x + xv.y * c0.y + xv.z * c0.z + xv.w * c0.w;
        d1 += xv.x * c1.x + xv.y * c1.y + xv.z * c1.z + xv.w * c1.w;
    }
#pragma unroll
    for (int o = 16; o; o >>= 1) {
        s0 += __shfl_xor_sync(0xffffffffu, s0, o);
        s1 += __shfl_xor_sync(0xffffffffu, s1, o);
        d0 += __shfl_xor_sync(0xffffffffu, d0, o);
        d1 += __shfl_xor_sync(0xffffffffu, d1, o);
    }
    if (lane == 0) {
        es[node * 2]     = s0;
        es[node * 2 + 1] = s1;
        ed[node * 2]     = d0;
        ed[node * 2 + 1] = d1;
    }
}

// ---------------- attention aggregate over RAW f32 features -------------------
// ONE WARP PER NODE, both heads share the gathered source row.
// Pass B batches 4 edges: all row loads issued before any FMA (MLP x4).
template <int K>
__global__ void k_agg(const float* __restrict__ feat, const float* __restrict__ es,
                      const float* __restrict__ ed,
                      fp16* __restrict__ ahi, fp16* __restrict__ alo) {
    constexpr int VEC = K / 32;      // floats per lane (4 or 8)
    constexpr int NF4 = VEC / 4;     // float4s per lane (1 or 2)
    int gt = blockIdx.x * blockDim.x + threadIdx.x;
    int node = gt >> 5, lane = gt & 31;
    if (node >= NN) return;
    int beg = g_off[node], end = g_off[node + 1];
    float edv0 = ed[node * 2], edv1 = ed[node * 2 + 1];

    // pass A: both heads' leaky logits per edge; stash interleaved; track maxes
    float m0 = -1e30f, m1 = -1e30f;
    for (int j = beg + lane; j < end; j += 32) {
        int s = g_csr[j];
        float2 esv = *(const float2*)(es + 2 * s);
        float e0 = esv.x + edv0; e0 = e0 > 0.f ? e0 : 0.2f * e0;
        float e1 = esv.y + edv1; e1 = e1 > 0.f ? e1 : 0.2f * e1;
        *(float2*)(g_ew + 2 * (size_t)j) = make_float2(e0, e1);
        m0 = fmaxf(m0, e0);
        m1 = fmaxf(m1, e1);
    }
#pragma unroll
    for (int o = 16; o; o >>= 1) {
        m0 = fmaxf(m0, __shfl_xor_sync(0xffffffffu, m0, o));
        m1 = fmaxf(m1, __shfl_xor_sync(0xffffffffu, m1, o));
    }

    // pass B: weighted accumulation, 4-edge load batches for MLP
    float acc0[VEC], acc1[VEC];
#pragma unroll
    for (int q = 0; q < VEC; q++) { acc0[q] = 0.f; acc1[q] = 0.f; }
    float ws0 = 0.f, ws1 = 0.f;

    for (int j0 = beg; j0 < end; j0 += 32) {
        int jj = j0 + lane;
        bool val = jj < end;
        int sl = val ? g_csr[jj] : 0;
        float wl0 = 0.f, wl1 = 0.f;
        if (val) {
            float2 e2 = *(const float2*)(g_ew + 2 * (size_t)jj);
            wl0 = __expf(e2.x - m0);
            wl1 = __expf(e2.y - m1);
        }
        ws0 += wl0; ws1 += wl1;
        int cnt = end - j0; if (cnt > 32) cnt = 32;

        for (int t = 0; t < cnt; t += 4) {
            int e = cnt - t; if (e > 4) e = 4;   // warp-uniform
            float w0[4], w1[4];
            float4 v[4][NF4];
#pragma unroll
            for (int j = 0; j < 4; j++) {
                if (j < e) {
                    int sv = __shfl_sync(0xffffffffu, sl, t + j);
                    w0[j]  = __shfl_sync(0xffffffffu, wl0, t + j);
                    w1[j]  = __shfl_sync(0xffffffffu, wl1, t + j);
                    const float4* p = (const float4*)(feat + (size_t)sv * K);
#pragma unroll
                    for (int q = 0; q < NF4; q++)
                        v[j][q] = __ldg(p + q * 32 + lane);
                }
            }
#pragma unroll
            for (int j = 0; j < 4; j++) {
                if (j < e) {
#pragma unroll
                    for (int q = 0; q < NF4; q++) {
                        acc0[4 * q + 0] += w0[j] * v[j][q].x;
                        acc0[4 * q + 1] += w0[j] * v[j][q].y;
                        acc0[4 * q + 2] += w0[j] * v[j][q].z;
                        acc0[4 * q + 3] += w0[j] * v[j][q].w;
                        acc1[4 * q + 0] += w1[j] * v[j][q].x;
                        acc1[4 * q + 1] += w1[j] * v[j][q].y;
                        acc1[4 * q + 2] += w1[j] * v[j][q].z;
                        acc1[4 * q + 3] += w1[j] * v[j][q].w;
                    }
                }
            }
        }
    }
#pragma unroll
    for (int o = 16; o; o >>= 1) {
        ws0 += __shfl_xor_sync(0xffffffffu, ws0, o);
        ws1 += __shfl_xor_sync(0xffffffffu, ws1, o);
    }
    float inv0 = 1.0f / (ws0 + 1e-16f);
    float inv1 = 1.0f / (ws1 + 1e-16f);

    // epilogue: normalize + fp16 hi/lo split; feature index = q*128 + lane*4 + i
#pragma unroll
    for (int hd = 0; hd < 2; hd++) {
        const float* av = hd ? acc1 : acc0;
        float inv = hd ? inv1 : inv0;
#pragma unroll
        for (int q = 0; q < NF4; q++) {
            size_t idx = (size_t)node * (2 * K) + hd * K + q * 128 + lane * 4;
            float r0 = av[4 * q + 0] * inv;
            float r1 = av[4 * q + 1] * inv;
            float r2 = av[4 * q + 2] * inv;
            float r3 = av[4 * q + 3] * inv;
            fp16 h0 = __float2half_rn(r0);
            fp16 h1 = __float2half_rn(r1);
            fp16 h2 = __float2half_rn(r2);
            fp16 h3 = __float2half_rn(r3);
            __half2* ph = (__half2*)(ahi + idx);
            ph[0] = __halves2half2(h0, h1);
            ph[1] = __halves2half2(h2, h3);
            __half2* pl = (__half2*)(alo + idx);
            pl[0] = __halves2half2(__float2half_rn(r0 - __half2float(h0)),
                                   __float2half_rn(r1 - __half2float(h1)));
            pl[1] = __halves2half2(__float2half_rn(r2 - __half2float(h2)),
                                   __float2half_rn(r3 - __half2float(h3)));
        }
    }
}

// ---------------- HMMA GEMM v5: per-head, fused bias+BN+ReLU epilogue ---------
#define RS 40              // smem row stride in 16-bit elems (80B, conflict-free)
#define ARRA 10240         // A array bytes (128*RS*2)
#define ARRB2 5120         // B array bytes (64*RS*2)
#define BUFB (2*ARRA + ARRB2)   // 25600 per buffer
#define OFF_AH 0
#define OFF_AL ARRA
#define OFF_BH (2*ARRA)

__global__ __launch_bounds__(256)
void k_mma(const fp16* __restrict__ Ahi, const fp16* __restrict__ Alo,
           const fp16* __restrict__ B, float* __restrict__ C,
           const float* __restrict__ sc, const float* __restrict__ sh,
           int M, int K, int CH) {
    extern __shared__ __align__(16) char smem[];

    const int tid = threadIdx.x, lane = tid & 31, wid = tid >> 5;
    const int bm = blockIdx.y * 128;
    const int z  = blockIdx.z;
    const int bnl = blockIdx.x * 64;
    const int ldA = 2 * K;
    const int wm = (wid & 3) * 32;
    const int wn = (wid >> 2) * 32;

    int arow[2];
    size_t aoff[2];
#pragma unroll
    for (int r = 0; r < 2; r++) {
        int idx = tid + r * 256;
        arow[r] = idx >> 2;
        int ra = bm + arow[r]; if (ra >= M) ra = M - 1;
        aoff[r] = (size_t)ra * ldA + z * K + (idx & 3) * 8;
    }
    const int brow = tid >> 2;
    const size_t boff = (size_t)(z * CH + bnl + brow) * K + (tid & 3) * 8;

    const uint32_t soA0 = (uint32_t)((arow[0] * RS + (tid & 3) * 8) * 2);
    const uint32_t soA1 = (uint32_t)((arow[1] * RS + ((tid + 256) & 3) * 8) * 2);
    const uint32_t soB  = (uint32_t)((brow * RS + (tid & 3) * 8) * 2);

    const int li = lane >> 3, l8 = lane & 7;
    const uint32_t aA = (uint32_t)(((wm + (li & 1) * 8 + l8) * RS + (li >> 1) * 8) * 2);
    const uint32_t aB = (uint32_t)(((wn + (li >> 1) * 8 + l8) * RS + (li & 1) * 8) * 2);
    const uint32_t base = s2u(smem);

    float acc[2][4][4];
#pragma unroll
    for (int i = 0; i < 2; i++)
#pragma unroll
        for (int j = 0; j < 4; j++)
#pragma unroll
            for (int k = 0; k < 4; k++) acc[i][j][k] = 0.f;

    uint4 pfA[2][2], pfB;
    const int nch = K >> 5;

#pragma unroll
    for (int r = 0; r < 2; r++) {
        pfA[0][r] = *(const uint4*)(Ahi + aoff[r]);
        pfA[1][r] = *(const uint4*)(Alo + aoff[r]);
    }
    pfB = *(const uint4*)(B + boff);

    for (int c = 0; c < nch; c++) {
        const uint32_t bufo = (uint32_t)((c & 1) * BUFB);
        char* pb = smem + bufo;
        *(uint4*)(pb + OFF_AH + soA0) = pfA[0][0];
        *(uint4*)(pb + OFF_AH + soA1) = pfA[0][1];
        *(uint4*)(pb + OFF_AL + soA0) = pfA[1][0];
        *(uint4*)(pb + OFF_AL + soA1) = pfA[1][1];
        *(uint4*)(pb + OFF_BH + soB)  = pfB;
        __syncthreads();

        if (c + 1 < nch) {
            size_t kadv = (size_t)(c + 1) * 32;
#pragma unroll
            for (int r = 0; r < 2; r++) {
                pfA[0][r] = *(const uint4*)(Ahi + aoff[r] + kadv);
                pfA[1][r] = *(const uint4*)(Alo + aoff[r] + kadv);
            }
            pfB = *(const uint4*)(B + boff + kadv);
        }

        const uint32_t bAh = base + bufo + OFF_AH + aA;
        const uint32_t bAl = base + bufo + OFF_AL + aA;
        const uint32_t bBh = base + bufo + OFF_BH + aB;

#pragma unroll
        for (int ks = 0; ks < 2; ks++) {
            const uint32_t kb = (uint32_t)(ks * 16 * 2);
            uint32_t ah[2][4], al[2][4], bh[2][4];
#pragma unroll
            for (int mt = 0; mt < 2; mt++) {
                uint32_t off = (uint32_t)(mt * 16 * RS * 2) + kb;
                ldsm4(ah[mt], bAh + off);
                ldsm4(al[mt], bAl + off);
            }
#pragma unroll
            for (int p = 0; p < 2; p++) {
                uint32_t off = (uint32_t)(p * 16 * RS * 2) + kb;
                ldsm4(bh[p], bBh + off);
            }
#pragma unroll
            for (int mt = 0; mt < 2; mt++)
#pragma unroll
                for (int nt = 0; nt < 4; nt++) {
                    const int p = nt >> 1, o = (nt & 1) * 2;
                    mma16816h(acc[mt][nt], ah[mt], bh[p][o], bh[p][o + 1]);
                    mma16816h(acc[mt][nt], al[mt], bh[p][o], bh[p][o + 1]);
                }
        }
        // no trailing sync: next iteration writes the OTHER buffer
    }

    const int Ntot = 2 * CH;
#pragma unroll
    for (int mt = 0; mt < 2; mt++) {
        int r0 = bm + wm + mt * 16 + (lane >> 2);
#pragma unroll
        for (int nt = 0; nt < 4; nt++) {
            int col = z * CH + bnl + wn + nt * 8 + (lane & 3) * 2;
            float s0 = sc[col], s1 = sc[col + 1];
            float t0 = sh[col], t1 = sh[col + 1];
            if (r0 < M)
                *(float2*)(C + (size_t)r0 * Ntot + col) = make_float2(
                    fmaxf(acc[mt][nt][0] * s0 + t0, 0.f),
                    fmaxf(acc[mt][nt][1] * s1 + t1, 0.f));
            if (r0 + 8 < M)
                *(float2*)(C + (size_t)(r0 + 8) * Ntot + col) = make_float2(
                    fmaxf(acc[mt][nt][2] * s0 + t0, 0.f),
                    fmaxf(acc[mt][nt][3] * s1 + t1, 0.f));
        }
    }
}

// ---------------- launch -----------------------------------------------------
extern "C" void kernel_launch(void* const* d_in, const int* in_sizes, int n_in,
                              void* d_out, int out_size) {
    const float* x   = (const float*)d_in[0];
    const int*   ei  = (const int*)d_in[1];
    const float* W1  = (const float*)d_in[2];
    const float* as1 = (const float*)d_in[3];
    const float* ad1 = (const float*)d_in[4];
    const float* b1  = (const float*)d_in[5];
    const float* g1  = (const float*)d_in[6];
    const float* be1 = (const float*)d_in[7];
    const float* m1  = (const float*)d_in[8];
    const float* v1  = (const float*)d_in[9];
    const float* W2  = (const float*)d_in[10];
    const float* as2 = (const float*)d_in[11];
    const float* ad2 = (const float*)d_in[12];
    const float* b2  = (const float*)d_in[13];
    const float* g2  = (const float*)d_in[14];
    const float* be2 = (const float*)d_in[15];
    const float* m2  = (const float*)d_in[16];
    const float* v2  = (const float*)d_in[17];
    float* out = (float*)d_out;

    const int* srcp = ei;
    const int* dstp = ei + NE;

    float *f1;
    cudaGetSymbolAddress((void**)&f1, g_f1);
    fp16 *a1hi, *a1lo, *a2hi, *a2lo, *w1, *w2;
    cudaGetSymbolAddress((void**)&a1hi, g_a1hi);
    cudaGetSymbolAddress((void**)&a1lo, g_a1lo);
    cudaGetSymbolAddress((void**)&a2hi, g_a2hi);
    cudaGetSymbolAddress((void**)&a2lo, g_a2lo);
    cudaGetSymbolAddress((void**)&w1, g_w1);
    cudaGetSymbolAddress((void**)&w2, g_w2);
    float *vas1, *vad1, *vas2, *vad2, *sc1, *sh1, *sc2, *sh2;
    cudaGetSymbolAddress((void**)&vas1, g_vas1);
    cudaGetSymbolAddress((void**)&vad1, g_vad1);
    cudaGetSymbolAddress((void**)&vas2, g_vas2);
    cudaGetSymbolAddress((void**)&vad2, g_vad2);
    cudaGetSymbolAddress((void**)&sc1, g_sc1);
    cudaGetSymbolAddress((void**)&sh1, g_sh1);
    cudaGetSymbolAddress((void**)&sc2, g_sc2);
    cudaGetSymbolAddress((void**)&sh2, g_sh2);
    float *es1, *ed1, *es2, *ed2;
    cudaGetSymbolAddress((void**)&es1, g_es1);
    cudaGetSymbolAddress((void**)&ed1, g_ed1);
    cudaGetSymbolAddress((void**)&es2, g_es2);
    cudaGetSymbolAddress((void**)&ed2, g_ed2);

    static bool attrSet = false;
    if (!attrSet) {
        cudaFuncSetAttribute(k_mma, cudaFuncAttributeMaxDynamicSharedMemorySize,
                             2 * BUFB);
        attrSet = true;
    }

    const int nodeWarpBlocks = (NN * 32 + 255) / 256;   // 6250 (warp per node)
    const int mTiles = (NN + 127) / 128;                // 391

    // conversions + prep
    k_cvtT<<<(128 * 256 + 255) / 256, 256>>>(W1, w1, 128, 256);
    k_cvtT<<<(256 * 512 + 255) / 256, 256>>>(W2, w2, 256, 512);
    k_pre0<<<(NN + 255) / 256, 256>>>(b1, g1, be1, m1, v1, b2, g2, be2, m2, v2);
    k_va<<<(768 * 32 + 255) / 256, 256>>>(W1, as1, ad1, W2, as2, ad2);

    // CSR build
    k_hist<<<(NET + 255) / 256, 256>>>(dstp);
    k_scan<<<1, 1024>>>();
    k_fill<<<(NET + 255) / 256, 256>>>(srcp, dstp);

    // layer 1: logits on x, aggregate x, then GEMM (+fused bias/BN/ReLU) -> f1
    k_edx<128><<<nodeWarpBlocks, 256>>>(x, vas1, vad1, es1, ed1);
    k_agg<128><<<nodeWarpBlocks, 256>>>(x, es1, ed1, a1hi, a1lo);
    k_mma<<<dim3(2, mTiles, 2), 256, 2 * BUFB>>>(a1hi, a1lo, w1, f1, sc1, sh1,
                                                 NN, 128, 128);

    // layer 2: logits on f1, aggregate f1, then GEMM -> out
    k_edx<256><<<nodeWarpBlocks, 256>>>(f1, vas2, vad2, es2, ed2);
    k_agg<256><<<nodeWarpBlocks, 256>>>(f1, es2, ed2, a2hi, a2lo);
    k_mma<<<dim3(4, mTiles, 2), 256, 2 * BUFB>>>(a2hi, a2lo, w2, out, sc2, sh2,
                                                 NN, 256, 256);
}

// round 17
// speedup vs baseline: 1.3615x; 1.3615x over previous
#include <cuda_runtime.h>
#include <cuda_fp16.h>
#include <cstdint>

#define NN  50000
#define NE  800000
#define NET 850000   // NE + NN self loops
#define NBLK 196     // ceil(NN/256)

typedef __half fp16;

// ---------------- scratch (static device globals; no allocs allowed) ----------
__device__ float g_f1[(size_t)NN * 256];     // layer-1 output (f32, gather source)
__device__ fp16  g_a1hi[(size_t)NN * 256], g_a1lo[(size_t)NN * 256];  // agg1 split
__device__ fp16  g_a2hi[(size_t)NN * 512], g_a2lo[(size_t)NN * 512];  // agg2 split
__device__ fp16  g_w1[256 * 128];            // W1^T [N=256,K=128] fp16
__device__ fp16  g_w2[512 * 256];            // W2^T [N=512,K=256] fp16
__device__ float g_vas1[2 * 128], g_vad1[2 * 128];   // W1_h @ a vectors
__device__ float g_vas2[2 * 256], g_vad2[2 * 256];
__device__ float g_sc1[256], g_sh1[256];     // fused bias+BN scale/shift
__device__ float g_sc2[512], g_sh2[512];
__device__ float g_es1[NN * 2], g_ed1[NN * 2];
__device__ float g_es2[NN * 2], g_ed2[NN * 2];
__device__ float g_ew[(size_t)2 * NET];      // per-edge (head0,head1) leaky logits
__device__ int   g_deg[NN];
__device__ int   g_off[NN + 1];
__device__ int   g_cur[NN];
__device__ int   g_csr[NET];                 // src per CSR slot (grouped by dst)
__device__ int   g_bsum[256];
__device__ int   g_bpre[256];

// ---------------- PTX helpers (arch-generic: ldmatrix + mma.sync) -------------
__device__ __forceinline__ uint32_t s2u(const void* p) {
    uint32_t a;
    asm("{ .reg .u64 t; cvta.to.shared.u64 t, %1; cvt.u32.u64 %0, t; }"
        : "=r"(a) : "l"(p));
    return a;
}

__device__ __forceinline__ void ldsm4(uint32_t* r, uint32_t addr) {
    asm volatile("ldmatrix.sync.aligned.m8n8.x4.shared.b16 {%0,%1,%2,%3}, [%4];"
                 : "=r"(r[0]), "=r"(r[1]), "=r"(r[2]), "=r"(r[3]) : "r"(addr));
}

__device__ __forceinline__ void mma16816h(float* d, const uint32_t* a,
                                          uint32_t b0, uint32_t b1) {
    asm volatile(
        "mma.sync.aligned.m16n8k16.row.col.f32.f16.f16.f32 "
        "{%0,%1,%2,%3}, {%4,%5,%6,%7}, {%8,%9}, {%0,%1,%2,%3};"
        : "+f"(d[0]), "+f"(d[1]), "+f"(d[2]), "+f"(d[3])
        : "r"(a[0]), "r"(a[1]), "r"(a[2]), "r"(a[3]), "r"(b0), "r"(b1));
}

// ---------------- W^T fp16 conversion -----------------------------------------
__global__ void k_cvtT(const float* __restrict__ W, fp16* __restrict__ T,
                       int K, int N) {
    int i = blockIdx.x * blockDim.x + threadIdx.x;
    if (i >= K * N) return;
    int k = i / N, n = i % N;
    T[(size_t)n * K + k] = __float2half_rn(W[i]);
}

// ---------------- prep 0: deg zero + BN coefs (elementwise) -------------------
__global__ void k_pre0(const float* __restrict__ b1, const float* __restrict__ g1,
                       const float* __restrict__ be1, const float* __restrict__ m1,
                       const float* __restrict__ v1,
                       const float* __restrict__ b2, const float* __restrict__ g2,
                       const float* __restrict__ be2, const float* __restrict__ m2,
                       const float* __restrict__ v2) {
    int i = blockIdx.x * blockDim.x + threadIdx.x;
    if (i < NN) g_deg[i] = 0;
    if (i < 256) {
        float sc = rsqrtf(v1[i] + 1e-5f) * g1[i];
        g_sc1[i] = sc;
        g_sh1[i] = (b1[i] - m1[i]) * sc + be1[i];
    }
    if (i >= 1024 && i < 1024 + 512) {
        int f = i - 1024;
        float sc = rsqrtf(v2[f] + 1e-5f) * g2[f];
        g_sc2[f] = sc;
        g_sh2[f] = (b2[f] - m2[f]) * sc + be2[f];
    }
}

// ---------------- va vectors: warp per output, lane-strided dot ---------------
__global__ void k_va(const float* __restrict__ W1, const float* __restrict__ as1,
                     const float* __restrict__ ad1,
                     const float* __restrict__ W2, const float* __restrict__ as2,
                     const float* __restrict__ ad2) {
    int gt = blockIdx.x * blockDim.x + threadIdx.x;
    int w = gt >> 5, lane = gt & 31;
    if (w >= 768) return;
    float s = 0.f, d = 0.f;
    if (w < 256) {
        int h = w >> 7, k = w & 127;
        const float* wr = W1 + (size_t)k * 256 + h * 128;
        const float* ar = as1 + h * 128;
        const float* dr = ad1 + h * 128;
#pragma unroll
        for (int c = lane; c < 128; c += 32) {
            float wv = wr[c];
            s += wv * ar[c];
            d += wv * dr[c];
        }
    } else {
        int j = w - 256, h = j >> 8, k = j & 255;
        const float* wr = W2 + (size_t)k * 512 + h * 256;
        const float* ar = as2 + h * 256;
        const float* dr = ad2 + h * 256;
#pragma unroll
        for (int c = lane; c < 256; c += 32) {
            float wv = wr[c];
            s += wv * ar[c];
            d += wv * dr[c];
        }
    }
#pragma unroll
    for (int o = 16; o; o >>= 1) {
        s += __shfl_xor_sync(0xffffffffu, s, o);
        d += __shfl_xor_sync(0xffffffffu, d, o);
    }
    if (lane == 0) {
        if (w < 256) { g_vas1[w] = s; g_vad1[w] = d; }
        else         { g_vas2[w - 256] = s; g_vad2[w - 256] = d; }
    }
}

// ---------------- CSR build: hist + PARALLEL scan + fill ----------------------
__global__ void k_hist(const int* __restrict__ dst) {
    int i = blockIdx.x * blockDim.x + threadIdx.x;
    if (i >= NET) return;
    int d = (i < NE) ? dst[i] : (i - NE);
    atomicAdd(&g_deg[d], 1);
}

__device__ __forceinline__ int blk_scan_excl(int v, int tid, int* wt) {
    int lane = tid & 31, w = tid >> 5;
    int inc = v;
#pragma unroll
    for (int o = 1; o < 32; o <<= 1) {
        int y = __shfl_up_sync(0xffffffffu, inc, o);
        if (lane >= o) inc += y;
    }
    if (lane == 31) wt[w] = inc;
    __syncthreads();
    if (w == 0) {
        int s = (lane < 8) ? wt[lane] : 0;
        int si = s;
#pragma unroll
        for (int o = 1; o < 8; o <<= 1) {
            int y = __shfl_up_sync(0xffffffffu, si, o);
            if (lane >= o) si += y;
        }
        if (lane < 8) wt[lane] = si - s;   // exclusive warp prefix
    }
    __syncthreads();
    return inc - v + wt[w];
}

__global__ void k_bsum() {
    __shared__ int wt[8];
    int b = blockIdx.x, t = threadIdx.x, i = b * 256 + t;
    int v = (i < NN) ? g_deg[i] : 0;
#pragma unroll
    for (int o = 16; o; o >>= 1) v += __shfl_xor_sync(0xffffffffu, v, o);
    if ((t & 31) == 0) wt[t >> 5] = v;
    __syncthreads();
    if (t == 0) {
        int s = 0;
#pragma unroll
        for (int q = 0; q < 8; q++) s += wt[q];
        g_bsum[b] = s;
    }
}

__global__ void k_bscan() {
    __shared__ int wt[8];
    int t = threadIdx.x;
    int v = (t < NBLK) ? g_bsum[t] : 0;
    int e = blk_scan_excl(v, t, wt);
    if (t < NBLK) g_bpre[t] = e;
    if (t == 0) g_off[NN] = NET;
}

__global__ void k_offs() {
    __shared__ int wt[8];
    int b = blockIdx.x, t = threadIdx.x, i = b * 256 + t;
    int v = (i < NN) ? g_deg[i] : 0;
    int e = blk_scan_excl(v, t, wt);
    if (i < NN) {
        int o = g_bpre[b] + e;
        g_off[i] = o;
        g_cur[i] = o;
    }
}

__global__ void k_fill(const int* __restrict__ src, const int* __restrict__ dst) {
    int i = blockIdx.x * blockDim.x + threadIdx.x;
    if (i >= NET) return;
    int s, d;
    if (i < NE) { s = src[i]; d = dst[i]; }
    else        { s = d = i - NE; }
    int pos = atomicAdd(&g_cur[d], 1);
    g_csr[pos] = s;
}

// ---------------- logits: es/ed = feat . va, warp per node, 4 dots ------------
template <int K>
__global__ void k_edx(const float* __restrict__ feat, const float* __restrict__ vas,
                      const float* __restrict__ vad, float* __restrict__ es,
                      float* __restrict__ ed) {
    constexpr int NF4 = K / 128;
    int gt = blockIdx.x * blockDim.x + threadIdx.x;
    int node = gt >> 5, lane = gt & 31;
    if (node >= NN) return;
    const float4* p = (const float4*)(feat + (size_t)node * K);
    float s0 = 0.f, d0 = 0.f, s1 = 0.f, d1 = 0.f;
#pragma unroll
    for (int q = 0; q < NF4; q++) {
        int idx4 = q * 32 + lane;
        float4 xv = p[idx4];
        float4 a0 = ((const float4*)(vas))[idx4];
        float4 a1 = ((const float4*)(vas + K))[idx4];
        float4 c0 = ((const float4*)(vad))[idx4];
        float4 c1 = ((const float4*)(vad + K))[idx4];
        s0 += xv.x * a0.x + xv.y * a0.y + xv.z * a0.z + xv.w * a0.w;
        s1 += xv.x * a1.x + xv.y * a1.y + xv.z * a1.z + xv.w * a1.w;
        d0 += xv.x * c0.x + xv.y * c0.y + xv.z * c0.z + xv.w * c0.w;
        d1 += xv.x * c1.x + xv.y * c1.y + xv.z * c1.z + xv.w * c1.w;
    }
#pragma unroll
    for (int o = 16; o; o >>= 1) {
        s0 += __shfl_xor_sync(0xffffffffu, s0, o);
        s1 += __shfl_xor_sync(0xffffffffu, s1, o);
        d0 += __shfl_xor_sync(0xffffffffu, d0, o);
        d1 += __shfl_xor_sync(0xffffffffu, d1, o);
    }
    if (lane == 0) {
        es[node * 2]     = s0;
        es[node * 2 + 1] = s1;
        ed[node * 2]     = d0;
        ed[node * 2 + 1] = d1;
    }
}

// ---------------- attention aggregate over RAW f32 features -------------------
// ONE WARP PER NODE, both heads share the gathered source row. (round-15 proven)
template <int K>
__global__ void k_agg(const float* __restrict__ feat, const float* __restrict__ es,
                      const float* __restrict__ ed,
                      fp16* __restrict__ ahi, fp16* __restrict__ alo) {
    constexpr int VEC = K / 32;      // floats per lane (4 or 8)
    constexpr int NF4 = VEC / 4;     // float4s per lane (1 or 2)
    int gt = blockIdx.x * blockDim.x + threadIdx.x;
    int node = gt >> 5, lane = gt & 31;
    if (node >= NN) return;
    int beg = g_off[node], end = g_off[node + 1];
    float edv0 = ed[node * 2], edv1 = ed[node * 2 + 1];

    // pass A: both heads' leaky logits per edge; stash interleaved; track maxes
    float m0 = -1e30f, m1 = -1e30f;
    for (int j = beg + lane; j < end; j += 32) {
        int s = g_csr[j];
        float2 esv = *(const float2*)(es + 2 * s);
        float e0 = esv.x + edv0; e0 = e0 > 0.f ? e0 : 0.2f * e0;
        float e1 = esv.y + edv1; e1 = e1 > 0.f ? e1 : 0.2f * e1;
        *(float2*)(g_ew + 2 * (size_t)j) = make_float2(e0, e1);
        m0 = fmaxf(m0, e0);
        m1 = fmaxf(m1, e1);
    }
#pragma unroll
    for (int o = 16; o; o >>= 1) {
        m0 = fmaxf(m0, __shfl_xor_sync(0xffffffffu, m0, o));
        m1 = fmaxf(m1, __shfl_xor_sync(0xffffffffu, m1, o));
    }

    // pass B: weighted accumulation of the shared source row, both heads
    float acc0[VEC], acc1[VEC];
#pragma unroll
    for (int q = 0; q < VEC; q++) { acc0[q] = 0.f; acc1[q] = 0.f; }
    float ws0 = 0.f, ws1 = 0.f;

    for (int j0 = beg; j0 < end; j0 += 32) {
        int jj = j0 + lane;
        bool val = jj < end;
        int sl = val ? g_csr[jj] : 0;
        float wl0 = 0.f, wl1 = 0.f;
        if (val) {
            float2 e2 = *(const float2*)(g_ew + 2 * (size_t)jj);
            wl0 = __expf(e2.x - m0);
            wl1 = __expf(e2.y - m1);
        }
        ws0 += wl0; ws1 += wl1;
        int cnt = end - j0; if (cnt > 32) cnt = 32;
        for (int t = 0; t < cnt; t++) {
            int   sv = __shfl_sync(0xffffffffu, sl, t);
            float w0 = __shfl_sync(0xffffffffu, wl0, t);
            float w1 = __shfl_sync(0xffffffffu, wl1, t);
            const float4* p = (const float4*)(feat + (size_t)sv * K);
#pragma unroll
            for (int q = 0; q < NF4; q++) {
                float4 v = __ldg(p + q * 32 + lane);
                acc0[4 * q + 0] += w0 * v.x; acc0[4 * q + 1] += w0 * v.y;
                acc0[4 * q + 2] += w0 * v.z; acc0[4 * q + 3] += w0 * v.w;
                acc1[4 * q + 0] += w1 * v.x; acc1[4 * q + 1] += w1 * v.y;
                acc1[4 * q + 2] += w1 * v.z; acc1[4 * q + 3] += w1 * v.w;
            }
        }
    }
#pragma unroll
    for (int o = 16; o; o >>= 1) {
        ws0 += __shfl_xor_sync(0xffffffffu, ws0, o);
        ws1 += __shfl_xor_sync(0xffffffffu, ws1, o);
    }
    float inv0 = 1.0f / (ws0 + 1e-16f);
    float inv1 = 1.0f / (ws1 + 1e-16f);

    // epilogue: normalize + fp16 hi/lo split; feature index = q*128 + lane*4 + i
#pragma unroll
    for (int hd = 0; hd < 2; hd++) {
        const float* av = hd ? acc1 : acc0;
        float inv = hd ? inv1 : inv0;
#pragma unroll
        for (int q = 0; q < NF4; q++) {
            size_t idx = (size_t)node * (2 * K) + hd * K + q * 128 + lane * 4;
            float r0 = av[4 * q + 0] * inv;
            float r1 = av[4 * q + 1] * inv;
            float r2 = av[4 * q + 2] * inv;
            float r3 = av[4 * q + 3] * inv;
            fp16 h0 = __float2half_rn(r0);
            fp16 h1 = __float2half_rn(r1);
            fp16 h2 = __float2half_rn(r2);
            fp16 h3 = __float2half_rn(r3);
            __half2* ph = (__half2*)(ahi + idx);
            ph[0] = __halves2half2(h0, h1);
            ph[1] = __halves2half2(h2, h3);
            __half2* pl = (__half2*)(alo + idx);
            pl[0] = __halves2half2(__float2half_rn(r0 - __half2float(h0)),
                                   __float2half_rn(r1 - __half2float(h1)));
            pl[1] = __halves2half2(__float2half_rn(r2 - __half2float(h2)),
                                   __float2half_rn(r3 - __half2float(h3)));
        }
    }
}

// ---------------- HMMA GEMM v5: per-head, fused bias+BN+ReLU epilogue ---------
#define RS 40              // smem row stride in 16-bit elems (80B, conflict-free)
#define ARRA 10240         // A array bytes (128*RS*2)
#define ARRB2 5120         // B array bytes (64*RS*2)
#define BUFB (2*ARRA + ARRB2)   // 25600 per buffer
#define OFF_AH 0
#define OFF_AL ARRA
#define OFF_BH (2*ARRA)

__global__ __launch_bounds__(256)
void k_mma(const fp16* __restrict__ Ahi, const fp16* __restrict__ Alo,
           const fp16* __restrict__ B, float* __restrict__ C,
           const float* __restrict__ sc, const float* __restrict__ sh,
           int M, int K, int CH) {
    extern __shared__ __align__(16) char smem[];

    const int tid = threadIdx.x, lane = tid & 31, wid = tid >> 5;
    const int bm = blockIdx.y * 128;
    const int z  = blockIdx.z;
    const int bnl = blockIdx.x * 64;
    const int ldA = 2 * K;
    const int wm = (wid & 3) * 32;
    const int wn = (wid >> 2) * 32;

    int arow[2];
    size_t aoff[2];
#pragma unroll
    for (int r = 0; r < 2; r++) {
        int idx = tid + r * 256;
        arow[r] = idx >> 2;
        int ra = bm + arow[r]; if (ra >= M) ra = M - 1;
        aoff[r] = (size_t)ra * ldA + z * K + (idx & 3) * 8;
    }
    const int brow = tid >> 2;
    const size_t boff = (size_t)(z * CH + bnl + brow) * K + (tid & 3) * 8;

    const uint32_t soA0 = (uint32_t)((arow[0] * RS + (tid & 3) * 8) * 2);
    const uint32_t soA1 = (uint32_t)((arow[1] * RS + ((tid + 256) & 3) * 8) * 2);
    const uint32_t soB  = (uint32_t)((brow * RS + (tid & 3) * 8) * 2);

    const int li = lane >> 3, l8 = lane & 7;
    const uint32_t aA = (uint32_t)(((wm + (li & 1) * 8 + l8) * RS + (li >> 1) * 8) * 2);
    const uint32_t aB = (uint32_t)(((wn + (li >> 1) * 8 + l8) * RS + (li & 1) * 8) * 2);
    const uint32_t base = s2u(smem);

    float acc[2][4][4];
#pragma unroll
    for (int i = 0; i < 2; i++)
#pragma unroll
        for (int j = 0; j < 4; j++)
#pragma unroll
            for (int k = 0; k < 4; k++) acc[i][j][k] = 0.f;

    uint4 pfA[2][2], pfB;
    const int nch = K >> 5;

#pragma unroll
    for (int r = 0; r < 2; r++) {
        pfA[0][r] = *(const uint4*)(Ahi + aoff[r]);
        pfA[1][r] = *(const uint4*)(Alo + aoff[r]);
    }
    pfB = *(const uint4*)(B + boff);

    for (int c = 0; c < nch; c++) {
        const uint32_t bufo = (uint32_t)((c & 1) * BUFB);
        char* pb = smem + bufo;
        *(uint4*)(pb + OFF_AH + soA0) = pfA[0][0];
        *(uint4*)(pb + OFF_AH + soA1) = pfA[0][1];
        *(uint4*)(pb + OFF_AL + soA0) = pfA[1][0];
        *(uint4*)(pb + OFF_AL + soA1) = pfA[1][1];
        *(uint4*)(pb + OFF_BH + soB)  = pfB;
        __syncthreads();

        if (c + 1 < nch) {
            size_t kadv = (size_t)(c + 1) * 32;
#pragma unroll
            for (int r = 0; r < 2; r++) {
                pfA[0][r] = *(const uint4*)(Ahi + aoff[r] + kadv);
                pfA[1][r] = *(const uint4*)(Alo + aoff[r] + kadv);
            }
            pfB = *(const uint4*)(B + boff + kadv);
        }

        const uint32_t bAh = base + bufo + OFF_AH + aA;
        const uint32_t bAl = base + bufo + OFF_AL + aA;
        const uint32_t bBh = base + bufo + OFF_BH + aB;

#pragma unroll
        for (int ks = 0; ks < 2; ks++) {
            const uint32_t kb = (uint32_t)(ks * 16 * 2);
            uint32_t ah[2][4], al[2][4], bh[2][4];
#pragma unroll
            for (int mt = 0; mt < 2; mt++) {
                uint32_t off = (uint32_t)(mt * 16 * RS * 2) + kb;
                ldsm4(ah[mt], bAh + off);
                ldsm4(al[mt], bAl + off);
            }
#pragma unroll
            for (int p = 0; p < 2; p++) {
                uint32_t off = (uint32_t)(p * 16 * RS * 2) + kb;
                ldsm4(bh[p], bBh + off);
            }
#pragma unroll
            for (int mt = 0; mt < 2; mt++)
#pragma unroll
                for (int nt = 0; nt < 4; nt++) {
                    const int p = nt >> 1, o = (nt & 1) * 2;
                    mma16816h(acc[mt][nt], ah[mt], bh[p][o], bh[p][o + 1]);
                    mma16816h(acc[mt][nt], al[mt], bh[p][o], bh[p][o + 1]);
                }
        }
        // no trailing sync: next iteration writes the OTHER buffer
    }

    const int Ntot = 2 * CH;
#pragma unroll
    for (int mt = 0; mt < 2; mt++) {
        int r0 = bm + wm + mt * 16 + (lane >> 2);
#pragma unroll
        for (int nt = 0; nt < 4; nt++) {
            int col = z * CH + bnl + wn + nt * 8 + (lane & 3) * 2;
            float s0 = sc[col], s1 = sc[col + 1];
            float t0 = sh[col], t1 = sh[col + 1];
            if (r0 < M)
                *(float2*)(C + (size_t)r0 * Ntot + col) = make_float2(
                    fmaxf(acc[mt][nt][0] * s0 + t0, 0.f),
                    fmaxf(acc[mt][nt][1] * s1 + t1, 0.f));
            if (r0 + 8 < M)
                *(float2*)(C + (size_t)(r0 + 8) * Ntot + col) = make_float2(
                    fmaxf(acc[mt][nt][2] * s0 + t0, 0.f),
                    fmaxf(acc[mt][nt][3] * s1 + t1, 0.f));
        }
    }
}

// ---------------- launch -----------------------------------------------------
extern "C" void kernel_launch(void* const* d_in, const int* in_sizes, int n_in,
                              void* d_out, int out_size) {
    const float* x   = (const float*)d_in[0];
    const int*   ei  = (const int*)d_in[1];
    const float* W1  = (const float*)d_in[2];
    const float* as1 = (const float*)d_in[3];
    const float* ad1 = (const float*)d_in[4];
    const float* b1  = (const float*)d_in[5];
    const float* g1  = (const float*)d_in[6];
    const float* be1 = (const float*)d_in[7];
    const float* m1  = (const float*)d_in[8];
    const float* v1  = (const float*)d_in[9];
    const float* W2  = (const float*)d_in[10];
    const float* as2 = (const float*)d_in[11];
    const float* ad2 = (const float*)d_in[12];
    const float* b2  = (const float*)d_in[13];
    const float* g2  = (const float*)d_in[14];
    const float* be2 = (const float*)d_in[15];
    const float* m2  = (const float*)d_in[16];
    const float* v2  = (const float*)d_in[17];
    float* out = (float*)d_out;

    const int* srcp = ei;
    const int* dstp = ei + NE;

    float *f1;
    cudaGetSymbolAddress((void**)&f1, g_f1);
    fp16 *a1hi, *a1lo, *a2hi, *a2lo, *w1, *w2;
    cudaGetSymbolAddress((void**)&a1hi, g_a1hi);
    cudaGetSymbolAddress((void**)&a1lo, g_a1lo);
    cudaGetSymbolAddress((void**)&a2hi, g_a2hi);
    cudaGetSymbolAddress((void**)&a2lo, g_a2lo);
    cudaGetSymbolAddress((void**)&w1, g_w1);
    cudaGetSymbolAddress((void**)&w2, g_w2);
    float *vas1, *vad1, *vas2, *vad2, *sc1, *sh1, *sc2, *sh2;
    cudaGetSymbolAddress((void**)&vas1, g_vas1);
    cudaGetSymbolAddress((void**)&vad1, g_vad1);
    cudaGetSymbolAddress((void**)&vas2, g_vas2);
    cudaGetSymbolAddress((void**)&vad2, g_vad2);
    cudaGetSymbolAddress((void**)&sc1, g_sc1);
    cudaGetSymbolAddress((void**)&sh1, g_sh1);
    cudaGetSymbolAddress((void**)&sc2, g_sc2);
    cudaGetSymbolAddress((void**)&sh2, g_sh2);
    float *es1, *ed1, *es2, *ed2;
    cudaGetSymbolAddress((void**)&es1, g_es1);
    cudaGetSymbolAddress((void**)&ed1, g_ed1);
    cudaGetSymbolAddress((void**)&es2, g_es2);
    cudaGetSymbolAddress((void**)&ed2, g_ed2);

    static bool attrSet = false;
    if (!attrSet) {
        cudaFuncSetAttribute(k_mma, cudaFuncAttributeMaxDynamicSharedMemorySize,
                             2 * BUFB);
        attrSet = true;
    }

    const int nodeWarpBlocks = (NN * 32 + 255) / 256;   // 6250 (warp per node)
    const int mTiles = (NN + 127) / 128;                // 391

    // conversions + prep
    k_cvtT<<<(128 * 256 + 255) / 256, 256>>>(W1, w1, 128, 256);
    k_cvtT<<<(256 * 512 + 255) / 256, 256>>>(W2, w2, 256, 512);
    k_pre0<<<(NN + 255) / 256, 256>>>(b1, g1, be1, m1, v1, b2, g2, be2, m2, v2);
    k_va<<<(768 * 32 + 255) / 256, 256>>>(W1, as1, ad1, W2, as2, ad2);

    // CSR build (parallel scan)
    k_hist<<<(NET + 255) / 256, 256>>>(dstp);
    k_bsum<<<NBLK, 256>>>();
    k_bscan<<<1, 256>>>();
    k_offs<<<NBLK, 256>>>();
    k_fill<<<(NET + 255) / 256, 256>>>(srcp, dstp);

    // layer 1: logits on x, aggregate x, then GEMM (+fused bias/BN/ReLU) -> f1
    k_edx<128><<<nodeWarpBlocks, 256>>>(x, vas1, vad1, es1, ed1);
    k_agg<128><<<nodeWarpBlocks, 256>>>(x, es1, ed1, a1hi, a1lo);
    k_mma<<<dim3(2, mTiles, 2), 256, 2 * BUFB>>>(a1hi, a1lo, w1, f1, sc1, sh1,
                                                 NN, 128, 128);

    // layer 2: logits on f1, aggregate f1, then GEMM -> out
    k_edx<256><<<nodeWarpBlocks, 256>>>(f1, vas2, vad2, es2, ed2);
    k_agg<256><<<nodeWarpBlocks, 256>>>(f1, es2, ed2, a2hi, a2lo);
    k_mma<<<dim3(4, mTiles, 2), 256, 2 * BUFB>>>(a2hi, a2lo, w2, out, sc2, sh2,
                                                 NN, 256, 256);
}